// round 12
// baseline (speedup 1.0000x reference)
#include <cuda_runtime.h>
#include <math.h>

// Problem constants (B=2, N=4096, C=256, K=64; hidden = 256, out = 256)
#define PB 2
#define PN 4096
#define PC 256
#define PK 64
#define NROW (PB * PK)       // 128 rows
#define NSEG 4               // point segments per row (pool phase)
#define SEG (PN / NSEG)      // 1024 points per segment
#define GRID 512             // = NROW * NSEG = 32 rowgroups * 16 outslices
#define THREADS 256

// Scratch (persistent device globals; no allocation)
__device__ float4   g_part4[NROW * NSEG * 64];   // pooled partial maxima
__device__ int      g_cnt[NROW * NSEG];
__device__ float4   g_h[NROW * 64];              // hidden activations
__device__ unsigned g_bar;                       // monotonic grid-barrier ticket

__device__ __forceinline__ void grid_barrier()
{
    __syncthreads();
    if (threadIdx.x == 0) {
        __threadfence();
        unsigned ticket = atomicAdd(&g_bar, 1u);
        unsigned target = ticket - (ticket % (unsigned)GRID) + (unsigned)GRID;
        unsigned v;
        do {
            asm volatile("ld.acquire.gpu.u32 %0, [%1];" : "=r"(v) : "l"(&g_bar) : "memory");
            if (v < target) __nanosleep(64);
        } while (v < target);
        __threadfence();
    }
    __syncthreads();
}

__global__ __launch_bounds__(THREADS)
void roi_onekernel(const float* __restrict__ points,   // (B, N, 3)
                   const float* __restrict__ feats,    // (B, N, C)
                   const float* __restrict__ props,    // (B, K, 7)
                   const float* __restrict__ W1,       // (C, 256)
                   const float* __restrict__ b1,
                   const float* __restrict__ W2,       // (256, 256)
                   const float* __restrict__ b2,
                   float* __restrict__ out)            // (B, K, 256)
{
    const int blk = blockIdx.x;
    const int t   = threadIdx.x;

    __shared__ int    s_idx[SEG];       // 4 KB
    __shared__ int    s_count;
    __shared__ float  s_box[6];
    __shared__ float4 s_part[256];      // 4 KB pool fold
    __shared__ float4 s_x[256];         // 4 KB: 4 rows x 64 f4 (mlp inputs)
    __shared__ float4 s_red[256];       // 4 KB reduction scratch
    __shared__ int    s_cnt4[4];

    // ================= Phase A: segment pooling =================
    {
        const int bk  = blk >> 2;        // row 0..127
        const int seg = blk & 3;
        const int b   = bk / PK;
        const int q   = t & 63;          // channel quad
        const int sl  = t >> 6;          // slice 0..3

        if (t == 0) s_count = 0;
        if (t < 3) {
            float c = props[bk * 7 + t];
            float h = props[bk * 7 + 3 + t] * 0.5f;
            s_box[t]     = c - h;
            s_box[t + 3] = c + h;
        }
        __syncthreads();

        const float lx = s_box[0], ly = s_box[1], lz = s_box[2];
        const float hx = s_box[3], hy = s_box[4], hz = s_box[5];

        const float* pb = points + (size_t)b * PN * 3;
        const int n0 = seg * SEG;
        #pragma unroll
        for (int it = 0; it < SEG / THREADS; it++) {
            int n = n0 + it * THREADS + t;
            float px = pb[n * 3 + 0];
            float py = pb[n * 3 + 1];
            float pz = pb[n * 3 + 2];
            bool inside = (px > lx) & (px < hx) &
                          (py > ly) & (py < hy) &
                          (pz > lz) & (pz < hz);
            if (inside) {
                int pos = atomicAdd(&s_count, 1);
                s_idx[pos] = n;
            }
        }
        __syncthreads();
        const int cnt = s_count;

        const float4* fb4 = (const float4*)(feats + (size_t)b * PN * PC);
        float4 acc = make_float4(-INFINITY, -INFINITY, -INFINITY, -INFINITY);
        {
            int i = sl;
            for (; i + 12 < cnt; i += 16) {
                int i0 = s_idx[i + 0];
                int i1 = s_idx[i + 4];
                int i2 = s_idx[i + 8];
                int i3 = s_idx[i + 12];
                float4 v0 = fb4[(size_t)i0 * 64 + q];
                float4 v1 = fb4[(size_t)i1 * 64 + q];
                float4 v2 = fb4[(size_t)i2 * 64 + q];
                float4 v3 = fb4[(size_t)i3 * 64 + q];
                acc.x = fmaxf(acc.x, fmaxf(fmaxf(v0.x, v1.x), fmaxf(v2.x, v3.x)));
                acc.y = fmaxf(acc.y, fmaxf(fmaxf(v0.y, v1.y), fmaxf(v2.y, v3.y)));
                acc.z = fmaxf(acc.z, fmaxf(fmaxf(v0.z, v1.z), fmaxf(v2.z, v3.z)));
                acc.w = fmaxf(acc.w, fmaxf(fmaxf(v0.w, v1.w), fmaxf(v2.w, v3.w)));
            }
            for (; i < cnt; i += 4) {
                float4 v = fb4[(size_t)s_idx[i] * 64 + q];
                acc.x = fmaxf(acc.x, v.x);
                acc.y = fmaxf(acc.y, v.y);
                acc.z = fmaxf(acc.z, v.z);
                acc.w = fmaxf(acc.w, v.w);
            }
        }
        s_part[t] = acc;
        __syncthreads();

        if (t < 64) {
            float4 a  = s_part[t];
            float4 c1 = s_part[64 + t];
            float4 c2 = s_part[128 + t];
            float4 c3 = s_part[192 + t];
            a.x = fmaxf(fmaxf(a.x, c1.x), fmaxf(c2.x, c3.x));
            a.y = fmaxf(fmaxf(a.y, c1.y), fmaxf(c2.y, c3.y));
            a.z = fmaxf(fmaxf(a.z, c1.z), fmaxf(c2.z, c3.z));
            a.w = fmaxf(fmaxf(a.w, c1.w), fmaxf(c2.w, c3.w));
            g_part4[(size_t)blk * 64 + t] = a;
        }
        if (t == 0) g_cnt[blk] = cnt;
    }

    grid_barrier();

    // ================= Phase B: layer 1 =================
    // CTA = (rowgroup r of 4 rows, out-slice s of 16 outputs). 512 CTAs.
    const int r = blk >> 4;          // 0..31
    const int s = blk & 15;          // 0..15
    {
        // fold NSEG pooled partials for my 4 rows into s_x
        const int rp = t >> 6, qq = t & 63;
        const int row = r * 4 + rp;
        float4 xa = g_part4[(size_t)row * (NSEG * 64) + qq];
        #pragma unroll
        for (int g = 1; g < NSEG; g++) {
            float4 c = g_part4[(size_t)row * (NSEG * 64) + g * 64 + qq];
            xa.x = fmaxf(xa.x, c.x);
            xa.y = fmaxf(xa.y, c.y);
            xa.z = fmaxf(xa.z, c.z);
            xa.w = fmaxf(xa.w, c.w);
        }
        if (t < 4) {
            int c = 0;
            #pragma unroll
            for (int i = 0; i < NSEG; i++) c += g_cnt[(r * 4 + t) * NSEG + i];
            s_cnt4[t] = c;
        }
        __syncthreads();
        if (s_cnt4[rp] == 0) xa = make_float4(0.f, 0.f, 0.f, 0.f);
        s_x[t] = xa;                 // s_x[rp*64 + qq]
        __syncthreads();

        // compute: thread (rp = t>>6, q = t&3, sl = (t&63)>>2)
        const int q  = t & 3;        // quad within my 16 outputs
        const int sl = (t & 63) >> 2;    // 16 slices x 16 c
        const float4* W4 = (const float4*)W1;
        const float*  xr = (const float*)(s_x + rp * 64);
        const int c0 = sl * 16;
        float4 a = make_float4(0.f, 0.f, 0.f, 0.f);
        #pragma unroll
        for (int c = 0; c < 16; c++) {
            float4 w = W4[(size_t)(c0 + c) * 64 + s * 4 + q];
            float f = xr[c0 + c];
            a.x = fmaf(f, w.x, a.x);
            a.y = fmaf(f, w.y, a.y);
            a.z = fmaf(f, w.z, a.z);
            a.w = fmaf(f, w.w, a.w);
        }
        s_red[t] = a;
        __syncthreads();

        if (t < 16) {
            const int r_ = t >> 2, q_ = t & 3;
            float4 acc = s_red[r_ * 64 + q_];
            #pragma unroll
            for (int g = 1; g < 16; g++) {
                float4 c = s_red[r_ * 64 + g * 4 + q_];
                acc.x += c.x; acc.y += c.y; acc.z += c.z; acc.w += c.w;
            }
            float4 bb = ((const float4*)b1)[s * 4 + q_];
            acc.x = fmaxf(acc.x + bb.x, 0.f);
            acc.y = fmaxf(acc.y + bb.y, 0.f);
            acc.z = fmaxf(acc.z + bb.z, 0.f);
            acc.w = fmaxf(acc.w + bb.w, 0.f);
            g_h[(size_t)(r * 4 + r_) * 64 + s * 4 + q_] = acc;
        }
    }

    grid_barrier();

    // ================= Phase C: layer 2 =================
    {
        const int rp = t >> 6;
        s_x[t] = g_h[(size_t)(r * 4 + rp) * 64 + (t & 63)];
        __syncthreads();

        const int q  = t & 3;
        const int sl = (t & 63) >> 2;
        const float4* W4 = (const float4*)W2;
        const float*  xr = (const float*)(s_x + rp * 64);
        const int c0 = sl * 16;
        float4 a = make_float4(0.f, 0.f, 0.f, 0.f);
        #pragma unroll
        for (int c = 0; c < 16; c++) {
            float4 w = W4[(size_t)(c0 + c) * 64 + s * 4 + q];
            float f = xr[c0 + c];
            a.x = fmaf(f, w.x, a.x);
            a.y = fmaf(f, w.y, a.y);
            a.z = fmaf(f, w.z, a.z);
            a.w = fmaf(f, w.w, a.w);
        }
        s_red[t] = a;
        __syncthreads();

        if (t < 16) {
            const int r_ = t >> 2, q_ = t & 3;
            float4 acc = s_red[r_ * 64 + q_];
            #pragma unroll
            for (int g = 1; g < 16; g++) {
                float4 c = s_red[r_ * 64 + g * 4 + q_];
                acc.x += c.x; acc.y += c.y; acc.z += c.z; acc.w += c.w;
            }
            float4 bb = ((const float4*)b2)[s * 4 + q_];
            acc.x = fmaxf(acc.x + bb.x, 0.f);
            acc.y = fmaxf(acc.y + bb.y, 0.f);
            acc.z = fmaxf(acc.z + bb.z, 0.f);
            acc.w = fmaxf(acc.w + bb.w, 0.f);
            ((float4*)out)[(size_t)(r * 4 + r_) * 64 + s * 4 + q_] = acc;
        }
    }
}

extern "C" void kernel_launch(void* const* d_in, const int* in_sizes, int n_in,
                              void* d_out, int out_size)
{
    const float* points = (const float*)d_in[0];   // (B, N, 3)
    const float* feats  = (const float*)d_in[1];   // (B, N, C)
    const float* props  = (const float*)d_in[2];   // (B, K, 7)
    const float* W1     = (const float*)d_in[3];   // (C, 256)
    const float* b1     = (const float*)d_in[4];   // (256)
    const float* W2     = (const float*)d_in[5];   // (256, 256)
    const float* b2     = (const float*)d_in[6];   // (256)
    float*       out    = (float*)d_out;           // (B, K, 256)

    roi_onekernel<<<GRID, THREADS>>>(points, feats, props, W1, b1, W2, b2, out);
}

// round 14
// speedup vs baseline: 1.3050x; 1.3050x over previous
#include <cuda_runtime.h>
#include <math.h>

// Problem constants (B=2, N=4096, C=256, K=64; hidden = 256, out = 256)
#define PB 2
#define PN 4096
#define PC 256
#define PK 64
#define NROW (PB * PK)       // 128
#define NS 8                 // split-K over points: 8 segments of 512 points
#define SEG (PN / NS)        // 512 points per segment

// Scratch
__device__ float4 g_part4[NROW * NS * 64];
__device__ int    g_cnt[NROW * NS];
__device__ float4 g_h[NROW * 64];     // hidden activations

// ---------------- Kernel A: segment pooling (R8-proven) ----------------
__global__ __launch_bounds__(256)
void pool_partial_kernel(const float* __restrict__ points,   // (B, N, 3)
                         const float* __restrict__ feats,    // (B, N, C)
                         const float* __restrict__ props)    // (B, K, 7)
{
    const int blk = blockIdx.x;      // bk * NS + s
    const int bk  = blk >> 3;
    const int s   = blk & (NS - 1);
    const int b   = bk / PK;
    const int t   = threadIdx.x;
    const int q   = t & 63;
    const int sl  = t >> 6;

    __shared__ int    s_idx[SEG];
    __shared__ int    s_count;
    __shared__ float  s_box[6];
    __shared__ float4 s_part[256];

    if (t == 0) s_count = 0;
    if (t < 3) {
        float c = props[bk * 7 + t];
        float h = props[bk * 7 + 3 + t] * 0.5f;
        s_box[t]     = c - h;
        s_box[t + 3] = c + h;
    }
    __syncthreads();

    const float lx = s_box[0], ly = s_box[1], lz = s_box[2];
    const float hx = s_box[3], hy = s_box[4], hz = s_box[5];

    const float* pb = points + (size_t)b * PN * 3;
    const int n0 = s * SEG;
    #pragma unroll
    for (int it = 0; it < SEG / 256; it++) {
        int n = n0 + it * 256 + t;
        float px = pb[n * 3 + 0];
        float py = pb[n * 3 + 1];
        float pz = pb[n * 3 + 2];
        bool inside = (px > lx) & (px < hx) &
                      (py > ly) & (py < hy) &
                      (pz > lz) & (pz < hz);
        if (inside) {
            int pos = atomicAdd(&s_count, 1);
            s_idx[pos] = n;
        }
    }
    __syncthreads();
    const int cnt = s_count;

    const float4* fb4 = (const float4*)(feats + (size_t)b * PN * PC);
    float4 acc = make_float4(-INFINITY, -INFINITY, -INFINITY, -INFINITY);
    {
        int i = sl;
        for (; i + 12 < cnt; i += 16) {
            int i0 = s_idx[i + 0];
            int i1 = s_idx[i + 4];
            int i2 = s_idx[i + 8];
            int i3 = s_idx[i + 12];
            float4 v0 = fb4[(size_t)i0 * 64 + q];
            float4 v1 = fb4[(size_t)i1 * 64 + q];
            float4 v2 = fb4[(size_t)i2 * 64 + q];
            float4 v3 = fb4[(size_t)i3 * 64 + q];
            acc.x = fmaxf(acc.x, fmaxf(fmaxf(v0.x, v1.x), fmaxf(v2.x, v3.x)));
            acc.y = fmaxf(acc.y, fmaxf(fmaxf(v0.y, v1.y), fmaxf(v2.y, v3.y)));
            acc.z = fmaxf(acc.z, fmaxf(fmaxf(v0.z, v1.z), fmaxf(v2.z, v3.z)));
            acc.w = fmaxf(acc.w, fmaxf(fmaxf(v0.w, v1.w), fmaxf(v2.w, v3.w)));
        }
        for (; i < cnt; i += 4) {
            float4 v = fb4[(size_t)s_idx[i] * 64 + q];
            acc.x = fmaxf(acc.x, v.x);
            acc.y = fmaxf(acc.y, v.y);
            acc.z = fmaxf(acc.z, v.z);
            acc.w = fmaxf(acc.w, v.w);
        }
    }
    s_part[t] = acc;
    __syncthreads();

    if (t < 64) {
        float4 a  = s_part[t];
        float4 c1 = s_part[64 + t];
        float4 c2 = s_part[128 + t];
        float4 c3 = s_part[192 + t];
        a.x = fmaxf(fmaxf(a.x, c1.x), fmaxf(c2.x, c3.x));
        a.y = fmaxf(fmaxf(a.y, c1.y), fmaxf(c2.y, c3.y));
        a.z = fmaxf(fmaxf(a.z, c1.z), fmaxf(c2.z, c3.z));
        a.w = fmaxf(fmaxf(a.w, c1.w), fmaxf(c2.w, c3.w));
        g_part4[(size_t)blk * 64 + t] = a;
    }
    if (t == 0) g_cnt[blk] = cnt;
}

// ---------------- Kernel B: clustered MLP ----------------
// Cluster of 8 CTAs owns 8 bk-rows. CTA rank p computes outputs [32p, 32p+32)
// for both layers; layer boundary = one cluster barrier through global g_h.
// Thread layout: q2 = t&7 (local out quad), sl = t>>3 (32 c-slices of 8).

__global__ __launch_bounds__(256) __cluster_dims__(8, 1, 1)
void mlp_cluster_kernel(const float* __restrict__ W1, const float* __restrict__ b1,
                        const float* __restrict__ W2, const float* __restrict__ b2,
                        float* __restrict__ out)
{
    const int t  = threadIdx.x;
    const int cl = blockIdx.x >> 3;      // cluster id 0..15
    const int p  = blockIdx.x & 7;       // rank / output slice
    const int r0 = cl * 8;               // first of 8 rows

    __shared__ float4 s_x[512];          // 8 rows x 64 quads (8 KB)
    __shared__ float4 s_red[2048];       // 32 KB: [rp][256]
    __shared__ int    s_cnt8[8];

    // ---- fold pooled partials for the 8 rows ----
    if (t < 8) {
        int c = 0;
        #pragma unroll
        for (int g = 0; g < NS; g++) c += g_cnt[(r0 + t) * NS + g];
        s_cnt8[t] = c;
    }
    float4 xa[2];
    #pragma unroll
    for (int k = 0; k < 2; k++) {
        int i = t + k * 256;
        int row = i >> 6, qq = i & 63;
        const float4* src = &g_part4[(size_t)(r0 + row) * (NS * 64)];
        float4 a = src[qq];
        #pragma unroll
        for (int g = 1; g < NS; g++) {
            float4 c = src[g * 64 + qq];
            a.x = fmaxf(a.x, c.x);
            a.y = fmaxf(a.y, c.y);
            a.z = fmaxf(a.z, c.z);
            a.w = fmaxf(a.w, c.w);
        }
        xa[k] = a;
    }
    __syncthreads();                     // s_cnt8 ready
    #pragma unroll
    for (int k = 0; k < 2; k++) {
        int i = t + k * 256;
        int row = i >> 6;
        float4 a = xa[k];
        if (s_cnt8[row] == 0) a = make_float4(0.f, 0.f, 0.f, 0.f);
        s_x[i] = a;
    }
    __syncthreads();

    const int q2   = t & 7;
    const int sl   = t >> 3;
    const int c0   = sl * 8;
    const int colq = p * 8 + q2;         // global output quad

    // ---- layer 1: 8 c's x 8 rows, W loaded once per (c, quad) ----
    {
        const float4* W4 = (const float4*)W1;
        const float*  xf = (const float*)s_x;
        float4 acc[8];
        #pragma unroll
        for (int r = 0; r < 8; r++) acc[r] = make_float4(0.f, 0.f, 0.f, 0.f);
        #pragma unroll
        for (int c = 0; c < 8; c++) {
            float4 w = W4[(size_t)(c0 + c) * 64 + colq];
            #pragma unroll
            for (int r = 0; r < 8; r++) {
                float f = xf[r * 256 + c0 + c];      // warp-uniform LDS
                acc[r].x = fmaf(f, w.x, acc[r].x);
                acc[r].y = fmaf(f, w.y, acc[r].y);
                acc[r].z = fmaf(f, w.z, acc[r].z);
                acc[r].w = fmaf(f, w.w, acc[r].w);
            }
        }
        #pragma unroll
        for (int r = 0; r < 8; r++) s_red[r * 256 + t] = acc[r];
    }
    __syncthreads();

    if (t < 64) {
        const int rp = t >> 3, qc = t & 7;
        float4 a = s_red[rp * 256 + qc];
        #pragma unroll
        for (int g = 1; g < 32; g++) {
            float4 c = s_red[rp * 256 + g * 8 + qc];
            a.x += c.x; a.y += c.y; a.z += c.z; a.w += c.w;
        }
        float4 bb = ((const float4*)b1)[p * 8 + qc];
        a.x = fmaxf(a.x + bb.x, 0.f);
        a.y = fmaxf(a.y + bb.y, 0.f);
        a.z = fmaxf(a.z + bb.z, 0.f);
        a.w = fmaxf(a.w + bb.w, 0.f);
        g_h[(size_t)(r0 + rp) * 64 + p * 8 + qc] = a;
    }
    __threadfence();                      // writer stores visible at gpu scope
    asm volatile("barrier.cluster.arrive.aligned;" ::: "memory");
    asm volatile("barrier.cluster.wait.aligned;"   ::: "memory");

    // ---- layer 2: read full hidden block from L2 ----
    #pragma unroll
    for (int k = 0; k < 2; k++) {
        int i = t + k * 256;
        int row = i >> 6, qq = i & 63;
        s_x[i] = __ldcg(&g_h[(size_t)(r0 + row) * 64 + qq]);
    }
    __syncthreads();

    {
        const float4* W4 = (const float4*)W2;
        const float*  xf = (const float*)s_x;
        float4 acc[8];
        #pragma unroll
        for (int r = 0; r < 8; r++) acc[r] = make_float4(0.f, 0.f, 0.f, 0.f);
        #pragma unroll
        for (int c = 0; c < 8; c++) {
            float4 w = W4[(size_t)(c0 + c) * 64 + colq];
            #pragma unroll
            for (int r = 0; r < 8; r++) {
                float f = xf[r * 256 + c0 + c];
                acc[r].x = fmaf(f, w.x, acc[r].x);
                acc[r].y = fmaf(f, w.y, acc[r].y);
                acc[r].z = fmaf(f, w.z, acc[r].z);
                acc[r].w = fmaf(f, w.w, acc[r].w);
            }
        }
        #pragma unroll
        for (int r = 0; r < 8; r++) s_red[r * 256 + t] = acc[r];
    }
    __syncthreads();

    if (t < 64) {
        const int rp = t >> 3, qc = t & 7;
        float4 a = s_red[rp * 256 + qc];
        #pragma unroll
        for (int g = 1; g < 32; g++) {
            float4 c = s_red[rp * 256 + g * 8 + qc];
            a.x += c.x; a.y += c.y; a.z += c.z; a.w += c.w;
        }
        float4 bb = ((const float4*)b2)[p * 8 + qc];
        a.x = fmaxf(a.x + bb.x, 0.f);
        a.y = fmaxf(a.y + bb.y, 0.f);
        a.z = fmaxf(a.z + bb.z, 0.f);
        a.w = fmaxf(a.w + bb.w, 0.f);
        ((float4*)out)[(size_t)(r0 + rp) * 64 + p * 8 + qc] = a;
    }
}

extern "C" void kernel_launch(void* const* d_in, const int* in_sizes, int n_in,
                              void* d_out, int out_size)
{
    const float* points = (const float*)d_in[0];   // (B, N, 3)
    const float* feats  = (const float*)d_in[1];   // (B, N, C)
    const float* props  = (const float*)d_in[2];   // (B, K, 7)
    const float* W1     = (const float*)d_in[3];   // (C, 256)
    const float* b1     = (const float*)d_in[4];   // (256)
    const float* W2     = (const float*)d_in[5];   // (256, 256)
    const float* b2     = (const float*)d_in[6];   // (256)
    float*       out    = (float*)d_out;           // (B, K, 256)

    pool_partial_kernel<<<NROW * NS, 256>>>(points, feats, props);
    mlp_cluster_kernel<<<NROW, 256>>>(W1, b1, W2, b2, out);
}